// round 4
// baseline (speedup 1.0000x reference)
#include <cuda_runtime.h>
#include <cuda_bf16.h>

// StrokeField: 2,097,152 points x 500 sequential sphere-stroke blends.
// Outputs concatenated in reference order: density [N], rgb [N,3], warped coords [N,3].

#define N_STROKES 500
#define N_POINTS  2097152
#define THREADS   256
#define PTS       4   // points per thread

__global__ __launch_bounds__(THREADS) void stroke_field_kernel(
    const float* __restrict__ coords,   // [N,3]
    const float* __restrict__ shape,    // [S,4] cx,cy,cz,r
    const float* __restrict__ color,    // [S,3]
    const float* __restrict__ alpha,    // [S,1]
    float* __restrict__ out)            // [7N]
{
    // Per-stroke constants, preprocessed once per block into shared:
    //  sG = (-2cx, -2cy, -2cz, |c|^2)   for d^2 = pp + |c|^2 - 2 p.c
    //  sH = (5r+0.5, density, colR, colG)   t = sat(5r+0.5 - 5d)
    //  sB = colB
    __shared__ float4 sG[N_STROKES];
    __shared__ float4 sH[N_STROKES];
    __shared__ float  sB[N_STROKES];

    const int tid = threadIdx.x;
    for (int s = tid; s < N_STROKES; s += THREADS) {
        float cx = shape[4*s+0], cy = shape[4*s+1], cz = shape[4*s+2], r = shape[4*s+3];
        sG[s] = make_float4(-2.f*cx, -2.f*cy, -2.f*cz,
                            fmaf(cx,cx, fmaf(cy,cy, cz*cz)));
        float a  = fmaf(5.f, r, 0.5f);
        float dp = fmaxf(alpha[s], 0.f) * 50.f;
        sH[s] = make_float4(a, dp, color[3*s+0], color[3*s+1]);
        sB[s] = color[3*s+2];
    }
    __syncthreads();

    const int base = blockIdx.x * (THREADS * PTS) + tid;

    float px[PTS], py[PTS], pz[PTS], pp[PTS];
    float hd[PTS], hr[PTS], hg[PTS], hb[PTS], hw[PTS];

    // Load + mip-NeRF-360 contraction, /2 warp.
    #pragma unroll
    for (int k = 0; k < PTS; k++) {
        int p = base + k * THREADS;
        float x = coords[3*p+0], y = coords[3*p+1], z = coords[3*p+2];
        float r2 = fmaf(x, x, fmaf(y, y, z * z));
        float rn; asm("sqrt.approx.ftz.f32 %0, %1;" : "=f"(rn) : "f"(r2));
        float n  = fmaxf(rn, 1e-9f);
        float iv; asm("rcp.approx.ftz.f32 %0, %1;" : "=f"(iv) : "f"(n));
        // inside unit ball: x/2; outside: (2 - 1/n)*x/n / 2. Continuous at n=1.
        float sc = (n <= 1.f) ? 0.5f : (2.f - iv) * iv * 0.5f;
        px[k] = x * sc; py[k] = y * sc; pz[k] = z * sc;
        pp[k] = fmaf(px[k], px[k], fmaf(py[k], py[k], pz[k] * pz[k]));
        hd[k] = 0.f; hr[k] = 0.f; hg[k] = 0.f; hb[k] = 0.f; hw[k] = 1.f;
    }

    // Sequential stroke blend (order matters, matches jax.lax.scan).
    #pragma unroll 2
    for (int s = 0; s < N_STROKES; s++) {
        const float4 G = sG[s];
        const float4 H = sH[s];
        const float  cb = sB[s];
        #pragma unroll
        for (int k = 0; k < PTS; k++) {
            float d2 = fmaf(px[k], G.x, fmaf(py[k], G.y, fmaf(pz[k], G.z, pp[k] + G.w)));
            d2 = fmaxf(d2, 0.f);                      // guard cancellation -> NaN
            float d; asm("sqrt.approx.ftz.f32 %0, %1;" : "=f"(d) : "f"(d2));
            float t = __saturatef(fmaf(d, -5.f, H.x)); // sat(5r+0.5-5d)
            float u = 1.f - t;
            hd[k] = fmaf(u, hd[k], t * H.y);
            hr[k] = fmaf(u, hr[k], t * H.z);
            hg[k] = fmaf(u, hg[k], t * H.w);
            hb[k] = fmaf(u, hb[k], t * cb);
            hw[k] *= u;
        }
    }

    // Epilogue: rgb = sat(h_color / (1+1e-6 - hw)), then write all three outputs.
    #pragma unroll
    for (int k = 0; k < PTS; k++) {
        int p = base + k * THREADS;
        float invd = 1.f / (1.000001f - hw[k]);
        out[p] = hd[k];
        out[N_POINTS + 3*p + 0] = __saturatef(hr[k] * invd);
        out[N_POINTS + 3*p + 1] = __saturatef(hg[k] * invd);
        out[N_POINTS + 3*p + 2] = __saturatef(hb[k] * invd);
        out[4*N_POINTS + 3*p + 0] = px[k];
        out[4*N_POINTS + 3*p + 1] = py[k];
        out[4*N_POINTS + 3*p + 2] = pz[k];
    }
}

extern "C" void kernel_launch(void* const* d_in, const int* in_sizes, int n_in,
                              void* d_out, int out_size) {
    const float* coords = (const float*)d_in[0];
    const float* shape  = (const float*)d_in[1];
    const float* color  = (const float*)d_in[2];
    const float* alpha  = (const float*)d_in[3];
    float* out = (float*)d_out;

    const int grid = N_POINTS / (THREADS * PTS); // 2048
    stroke_field_kernel<<<grid, THREADS>>>(coords, shape, color, alpha, out);
}

// round 5
// speedup vs baseline: 1.0609x; 1.0609x over previous
#include <cuda_runtime.h>
#include <cuda_bf16.h>

// StrokeField: 2,097,152 points x 500 sequential sphere-stroke blends.
// f32x2-packed inner loop: 2 points per packed register lane-pair.
// Outputs: density [N], rgb [N,3], warped coords [N,3] concatenated.

#define N_STROKES 500
#define N_POINTS  2097152
#define THREADS   256
#define PTS       4   // points per thread (2 packed pairs)
#define PAIRS     (PTS/2)

typedef unsigned long long u64;

__device__ __forceinline__ u64 pack2(float lo, float hi) {
    u64 r; asm("mov.b64 %0, {%1,%2};" : "=l"(r) : "f"(lo), "f"(hi)); return r;
}
__device__ __forceinline__ void unpack2(u64 v, float& lo, float& hi) {
    asm("mov.b64 {%0,%1}, %2;" : "=f"(lo), "=f"(hi) : "l"(v));
}
__device__ __forceinline__ u64 fma2(u64 a, u64 b, u64 c) {
    u64 d; asm("fma.rn.f32x2 %0, %1, %2, %3;" : "=l"(d) : "l"(a), "l"(b), "l"(c)); return d;
}
__device__ __forceinline__ u64 mul2(u64 a, u64 b) {
    u64 d; asm("mul.rn.f32x2 %0, %1, %2;" : "=l"(d) : "l"(a), "l"(b)); return d;
}
__device__ __forceinline__ u64 add2(u64 a, u64 b) {
    u64 d; asm("add.rn.f32x2 %0, %1, %2;" : "=l"(d) : "l"(a), "l"(b)); return d;
}
__device__ __forceinline__ float sqrt_approx(float x) {
    float r; asm("sqrt.approx.ftz.f32 %0, %1;" : "=f"(r) : "f"(x)); return r;
}
__device__ __forceinline__ float rcp_approx(float x) {
    float r; asm("rcp.approx.ftz.f32 %0, %1;" : "=f"(r) : "f"(x)); return r;
}

__global__ __launch_bounds__(THREADS) void stroke_field_kernel(
    const float* __restrict__ coords,   // [N,3]
    const float* __restrict__ shape,    // [S,4] cx,cy,cz,r
    const float* __restrict__ color,    // [S,3]
    const float* __restrict__ alpha,    // [S,1]
    float* __restrict__ out)            // [7N]
{
    // Pre-duplicated broadcast pairs in shared (LDS.128 -> two b64 regs, no packs):
    //  sG1[s] = {(Gx,Gx),(Gy,Gy)}  sG2[s] = {(Gz,Gz),(Gw,Gw)}
    //    with G = (-2cx,-2cy,-2cz, |c|^2)   so d^2 = pp + G.w + p.G
    //  sC1[s] = {(dp,dp),(cR,cR)}  sC2[s] = {(cG,cG),(cB,cB)}
    //  sA[s]  = 5r + 0.5   (t = sat(a - 5d))
    __shared__ ulonglong2 sG1[N_STROKES];
    __shared__ ulonglong2 sG2[N_STROKES];
    __shared__ ulonglong2 sC1[N_STROKES];
    __shared__ ulonglong2 sC2[N_STROKES];
    __shared__ float      sA[N_STROKES];

    const int tid = threadIdx.x;
    for (int s = tid; s < N_STROKES; s += THREADS) {
        float cx = shape[4*s+0], cy = shape[4*s+1], cz = shape[4*s+2], r = shape[4*s+3];
        float gx = -2.f*cx, gy = -2.f*cy, gz = -2.f*cz;
        float gw = fmaf(cx,cx, fmaf(cy,cy, cz*cz));
        float dp = fmaxf(alpha[s], 0.f) * 50.f;
        float cR = color[3*s+0], cG = color[3*s+1], cB = color[3*s+2];
        float* f;
        f = (float*)&sG1[s]; f[0]=gx; f[1]=gx; f[2]=gy; f[3]=gy;
        f = (float*)&sG2[s]; f[0]=gz; f[1]=gz; f[2]=gw; f[3]=gw;
        f = (float*)&sC1[s]; f[0]=dp; f[1]=dp; f[2]=cR; f[3]=cR;
        f = (float*)&sC2[s]; f[0]=cG; f[1]=cG; f[2]=cB; f[3]=cB;
        sA[s] = fmaf(5.f, r, 0.5f);
    }
    __syncthreads();

    const int base = blockIdx.x * (THREADS * PTS) + tid;

    u64 X2[PAIRS], Y2[PAIRS], Z2[PAIRS], PP2[PAIRS];
    u64 hd2[PAIRS], hr2[PAIRS], hg2[PAIRS], hb2[PAIRS], hw2[PAIRS];

    // Load + mip-NeRF-360 contraction (/2 warp), pack point pairs.
    #pragma unroll
    for (int i = 0; i < PAIRS; i++) {
        float px[2], py[2], pz[2], pp[2];
        #pragma unroll
        for (int j = 0; j < 2; j++) {
            int p = base + (2*i + j) * THREADS;
            float x = coords[3*p+0], y = coords[3*p+1], z = coords[3*p+2];
            float r2 = fmaf(x, x, fmaf(y, y, z*z));
            float n  = fmaxf(sqrt_approx(r2), 1e-9f);
            float iv = rcp_approx(n);
            // inside unit ball: x/2; outside: (2 - 1/n)*x/n / 2. Continuous at n=1.
            float sc = (n <= 1.f) ? 0.5f : (2.f - iv) * iv * 0.5f;
            px[j] = x * sc; py[j] = y * sc; pz[j] = z * sc;
            pp[j] = fmaf(px[j], px[j], fmaf(py[j], py[j], pz[j]*pz[j]));
        }
        X2[i] = pack2(px[0], px[1]);
        Y2[i] = pack2(py[0], py[1]);
        Z2[i] = pack2(pz[0], pz[1]);
        PP2[i] = pack2(pp[0], pp[1]);
        hd2[i] = 0ull; hr2[i] = 0ull; hg2[i] = 0ull; hb2[i] = 0ull;
        hw2[i] = pack2(1.f, 1.f);
    }

    const u64 ONE2    = pack2(1.f, 1.f);
    const u64 NEGONE2 = pack2(-1.f, -1.f);

    // Sequential stroke blend (order matters, matches jax.lax.scan).
    #pragma unroll 2
    for (int s = 0; s < N_STROKES; s++) {
        const ulonglong2 g1 = sG1[s];     // (Gx2, Gy2)
        const ulonglong2 g2 = sG2[s];     // (Gz2, Gw2)
        const ulonglong2 c1 = sC1[s];     // (DP2, CR2)
        const ulonglong2 c2 = sC2[s];     // (CG2, CB2)
        const float a = sA[s];
        #pragma unroll
        for (int i = 0; i < PAIRS; i++) {
            u64 d2p = fma2(X2[i], g1.x,
                      fma2(Y2[i], g1.y,
                      fma2(Z2[i], g2.x, add2(PP2[i], g2.y))));
            float d2lo, d2hi; unpack2(d2p, d2lo, d2hi);
            // |d2| guards rounding cancellation near d=0 (true d~0 -> t=sat(a), correct)
            float dlo = sqrt_approx(fabsf(d2lo));
            float dhi = sqrt_approx(fabsf(d2hi));
            float tlo = __saturatef(fmaf(dlo, -5.f, a));
            float thi = __saturatef(fmaf(dhi, -5.f, a));
            u64 t2 = pack2(tlo, thi);
            u64 u2 = fma2(t2, NEGONE2, ONE2);   // 1 - t
            hd2[i] = fma2(u2, hd2[i], mul2(t2, c1.x));
            hr2[i] = fma2(u2, hr2[i], mul2(t2, c1.y));
            hg2[i] = fma2(u2, hg2[i], mul2(t2, c2.x));
            hb2[i] = fma2(u2, hb2[i], mul2(t2, c2.y));
            hw2[i] = mul2(u2, hw2[i]);
        }
    }

    // Epilogue: rgb = sat(h_color / (1+1e-6 - hw)); write density, rgb, warped coords.
    #pragma unroll
    for (int i = 0; i < PAIRS; i++) {
        float hd[2], hr[2], hg[2], hb[2], hw[2], px[2], py[2], pz[2];
        unpack2(hd2[i], hd[0], hd[1]);
        unpack2(hr2[i], hr[0], hr[1]);
        unpack2(hg2[i], hg[0], hg[1]);
        unpack2(hb2[i], hb[0], hb[1]);
        unpack2(hw2[i], hw[0], hw[1]);
        unpack2(X2[i], px[0], px[1]);
        unpack2(Y2[i], py[0], py[1]);
        unpack2(Z2[i], pz[0], pz[1]);
        #pragma unroll
        for (int j = 0; j < 2; j++) {
            int p = base + (2*i + j) * THREADS;
            float invd = 1.f / (1.000001f - hw[j]);
            out[p] = hd[j];
            out[N_POINTS + 3*p + 0] = __saturatef(hr[j] * invd);
            out[N_POINTS + 3*p + 1] = __saturatef(hg[j] * invd);
            out[N_POINTS + 3*p + 2] = __saturatef(hb[j] * invd);
            out[4*N_POINTS + 3*p + 0] = px[j];
            out[4*N_POINTS + 3*p + 1] = py[j];
            out[4*N_POINTS + 3*p + 2] = pz[j];
        }
    }
}

extern "C" void kernel_launch(void* const* d_in, const int* in_sizes, int n_in,
                              void* d_out, int out_size) {
    const float* coords = (const float*)d_in[0];
    const float* shape  = (const float*)d_in[1];
    const float* color  = (const float*)d_in[2];
    const float* alpha  = (const float*)d_in[3];
    float* out = (float*)d_out;

    const int grid = N_POINTS / (THREADS * PTS); // 2048
    stroke_field_kernel<<<grid, THREADS>>>(coords, shape, color, alpha, out);
}

// round 6
// speedup vs baseline: 2.1714x; 2.0466x over previous
#include <cuda_runtime.h>
#include <cuda_bf16.h>

// StrokeField with spatial binning: strokes only touch points within d < r+0.1,
// so bin points into a 16^3 grid over contracted space, build per-cell stroke
// lists (order-preserving), and blend only relevant strokes per point.
// Skipped strokes have t=0 exactly => identity on all accumulators.

#define N_POINTS  2097152
#define N_STROKES 500
#define NC        16
#define NCELLS    (NC*NC*NC)          // 4096
#define MAXL      N_STROKES
#define CH        512                  // points per K5 block
#define NB5       (N_POINTS/CH)        // 4096 blocks
#define NTHREADS  256

// ---------------- scratch (device globals: allocation-free) ----------------
__device__ int    g_cellid[N_POINTS];        // cell per original point
__device__ int    g_hist[NCELLS];
__device__ int    g_start[NCELLS + 1];       // exclusive prefix (cell start)
__device__ int    g_cursor[NCELLS];          // scatter cursors
__device__ float4 g_cwp[N_POINTS];           // permuted (x,y,z,|p|^2)
__device__ int    g_orig[N_POINTS];          // permuted -> original index
__device__ int    g_cellp[N_POINTS];         // permuted -> cell id
__device__ int    g_listCount[NCELLS];
__device__ int    g_list[NCELLS * MAXL];     // per-cell stroke indices (ascending)
__device__ float4 g_scG[N_STROKES];          // (-2cx,-2cy,-2cz,|c|^2)
__device__ float4 g_scH[N_STROKES];          // (5r+0.5, density, colR, colG)
__device__ float  g_scB[N_STROKES];          // colB

__device__ __forceinline__ float sqrt_approx(float x) {
    float r; asm("sqrt.approx.ftz.f32 %0, %1;" : "=f"(r) : "f"(x)); return r;
}
__device__ __forceinline__ float rcp_approx(float x) {
    float r; asm("rcp.approx.ftz.f32 %0, %1;" : "=f"(r) : "f"(x)); return r;
}

// ---------------- K0: zero histogram ----------------
__global__ void k0_zero() {
    int i = blockIdx.x * blockDim.x + threadIdx.x;
    if (i < NCELLS) g_hist[i] = 0;
}

// ---------------- K1: contract coords, write warped output, bin ----------------
__global__ __launch_bounds__(NTHREADS) void k1_warp_bin(
    const float* __restrict__ coords, float* __restrict__ out)
{
    int p = blockIdx.x * NTHREADS + threadIdx.x;
    float x = coords[3*p+0], y = coords[3*p+1], z = coords[3*p+2];
    float r2 = fmaf(x, x, fmaf(y, y, z*z));
    float n  = fmaxf(sqrt_approx(r2), 1e-9f);
    float iv = rcp_approx(n);
    // contract: identity inside unit ball, (2-1/n)*x/n outside; then /2. Continuous at n=1.
    float sc = (n <= 1.f) ? 0.5f : (2.f - iv) * iv * 0.5f;
    float cx = x * sc, cy = y * sc, cz = z * sc;
    out[4*N_POINTS + 3*p + 0] = cx;
    out[4*N_POINTS + 3*p + 1] = cy;
    out[4*N_POINTS + 3*p + 2] = cz;
    // cell in [-1,1)^3 (|c| < 1 always)
    int ix = min(max((int)((cx + 1.f) * (NC * 0.5f)), 0), NC - 1);
    int iy = min(max((int)((cy + 1.f) * (NC * 0.5f)), 0), NC - 1);
    int iz = min(max((int)((cz + 1.f) * (NC * 0.5f)), 0), NC - 1);
    int cell = (ix * NC + iy) * NC + iz;
    g_cellid[p] = cell;
    atomicAdd(&g_hist[cell], 1);
}

// ---------------- K2: exclusive scan of bins + stroke constants ----------------
__global__ __launch_bounds__(512) void k2_scan_const(
    const float* __restrict__ shape, const float* __restrict__ color,
    const float* __restrict__ alpha)
{
    __shared__ int partial[512];
    int t = threadIdx.x;
    int base = t * (NCELLS / 512);   // 8 bins each
    int loc[8]; int sum = 0;
    #pragma unroll
    for (int i = 0; i < 8; i++) { loc[i] = sum; sum += g_hist[base + i]; }
    partial[t] = sum;
    __syncthreads();
    // Hillis-Steele inclusive scan
    for (int off = 1; off < 512; off <<= 1) {
        int v = (t >= off) ? partial[t - off] : 0;
        __syncthreads();
        partial[t] += v;
        __syncthreads();
    }
    int offset = (t > 0) ? partial[t - 1] : 0;
    #pragma unroll
    for (int i = 0; i < 8; i++) {
        g_start[base + i]  = offset + loc[i];
        g_cursor[base + i] = offset + loc[i];
    }
    if (t == 0) g_start[NCELLS] = N_POINTS;

    if (t < N_STROKES) {
        float cx = shape[4*t+0], cy = shape[4*t+1], cz = shape[4*t+2], r = shape[4*t+3];
        g_scG[t] = make_float4(-2.f*cx, -2.f*cy, -2.f*cz,
                               fmaf(cx,cx, fmaf(cy,cy, cz*cz)));
        float dp = fmaxf(alpha[t], 0.f) * 50.f;
        g_scH[t] = make_float4(fmaf(5.f, r, 0.5f), dp, color[3*t+0], color[3*t+1]);
        g_scB[t] = color[3*t+2];
    }
}

// ---------------- K3: counting-sort scatter ----------------
__global__ __launch_bounds__(NTHREADS) void k3_scatter(const float* __restrict__ out)
{
    int p = blockIdx.x * NTHREADS + threadIdx.x;
    int cell = g_cellid[p];
    int pos = atomicAdd(&g_cursor[cell], 1);
    float cx = out[4*N_POINTS + 3*p + 0];
    float cy = out[4*N_POINTS + 3*p + 1];
    float cz = out[4*N_POINTS + 3*p + 2];
    float pp = fmaf(cx, cx, fmaf(cy, cy, cz*cz));
    g_cwp[pos]   = make_float4(cx, cy, cz, pp);
    g_orig[pos]  = p;
    g_cellp[pos] = cell;
}

// ---------------- K4: per-cell stroke lists (warp ballot, order preserved) ----------------
__global__ __launch_bounds__(NTHREADS) void k4_lists(const float* __restrict__ shape)
{
    int warp = (blockIdx.x * NTHREADS + threadIdx.x) >> 5;
    int lane = threadIdx.x & 31;
    if (warp >= NCELLS) return;
    int iz = warp % NC, iy = (warp / NC) % NC, ix = warp / (NC * NC);
    const float w = 2.f / NC;
    float lox = -1.f + ix * w, hix = lox + w;
    float loy = -1.f + iy * w, hiy = loy + w;
    float loz = -1.f + iz * w, hiz = loz + w;
    int count = 0;
    for (int s0 = 0; s0 < N_STROKES; s0 += 32) {
        int s = s0 + lane;
        bool pred = false;
        if (s < N_STROKES) {
            float cx = shape[4*s+0], cy = shape[4*s+1], cz = shape[4*s+2], r = shape[4*s+3];
            float dx = fmaxf(fmaxf(lox - cx, cx - hix), 0.f);
            float dy = fmaxf(fmaxf(loy - cy, cy - hiy), 0.f);
            float dz = fmaxf(fmaxf(loz - cz, cz - hiz), 0.f);
            float d2 = fmaf(dx, dx, fmaf(dy, dy, dz*dz));
            float rr = r + 0.101f;           // band r+0.1 plus margin for approx sqrt
            pred = d2 < rr * rr;
        }
        unsigned m = __ballot_sync(0xffffffffu, pred);
        if (pred) {
            int off = count + __popc(m & ((1u << lane) - 1u));
            g_list[warp * MAXL + off] = s;
        }
        count += __popc(m);
    }
    if (lane == 0) g_listCount[warp] = count;
}

// ---------------- K5: main blend over sorted points ----------------
__global__ __launch_bounds__(NTHREADS) void k5_blend(float* __restrict__ out)
{
    __shared__ float4 shG[MAXL];
    __shared__ float4 shH[MAXL];
    __shared__ float  shB[MAXL];

    const int tid = threadIdx.x;
    int pos = blockIdx.x * CH;
    const int end = pos + CH;

    while (pos < end) {
        int cell   = g_cellp[pos];
        int segEnd = min(end, g_start[cell + 1]);
        int nl     = g_listCount[cell];
        for (int i = tid; i < nl; i += NTHREADS) {
            int s = g_list[cell * MAXL + i];
            shG[i] = g_scG[s];
            shH[i] = g_scH[s];
            shB[i] = g_scB[s];
        }
        __syncthreads();

        // 2 points per thread for ILP
        for (int q0 = pos + tid; q0 < segEnd; q0 += 2 * NTHREADS) {
            int q1 = q0 + NTHREADS;
            bool has1 = q1 < segEnd;
            float4 c0 = g_cwp[q0];
            float4 c1 = has1 ? g_cwp[q1] : c0;
            float hd0=0.f, hr0=0.f, hg0=0.f, hb0=0.f, hw0=1.f;
            float hd1=0.f, hr1=0.f, hg1=0.f, hb1=0.f, hw1=1.f;
            for (int i = 0; i < nl; i++) {
                float4 G = shG[i];
                float4 H = shH[i];
                float cb = shB[i];
                float d20 = fmaf(c0.x, G.x, fmaf(c0.y, G.y, fmaf(c0.z, G.z, c0.w + G.w)));
                float d21 = fmaf(c1.x, G.x, fmaf(c1.y, G.y, fmaf(c1.z, G.z, c1.w + G.w)));
                float d0 = sqrt_approx(fabsf(d20));
                float d1 = sqrt_approx(fabsf(d21));
                float t0 = __saturatef(fmaf(d0, -5.f, H.x));
                float t1 = __saturatef(fmaf(d1, -5.f, H.x));
                float u0 = 1.f - t0, u1 = 1.f - t1;
                hd0 = fmaf(u0, hd0, t0 * H.y);  hd1 = fmaf(u1, hd1, t1 * H.y);
                hr0 = fmaf(u0, hr0, t0 * H.z);  hr1 = fmaf(u1, hr1, t1 * H.z);
                hg0 = fmaf(u0, hg0, t0 * H.w);  hg1 = fmaf(u1, hg1, t1 * H.w);
                hb0 = fmaf(u0, hb0, t0 * cb);   hb1 = fmaf(u1, hb1, t1 * cb);
                hw0 *= u0;                      hw1 *= u1;
            }
            {
                int p = g_orig[q0];
                float invd = 1.f / (1.000001f - hw0);
                out[p] = hd0;
                out[N_POINTS + 3*p + 0] = __saturatef(hr0 * invd);
                out[N_POINTS + 3*p + 1] = __saturatef(hg0 * invd);
                out[N_POINTS + 3*p + 2] = __saturatef(hb0 * invd);
            }
            if (has1) {
                int p = g_orig[q1];
                float invd = 1.f / (1.000001f - hw1);
                out[p] = hd1;
                out[N_POINTS + 3*p + 0] = __saturatef(hr1 * invd);
                out[N_POINTS + 3*p + 1] = __saturatef(hg1 * invd);
                out[N_POINTS + 3*p + 2] = __saturatef(hb1 * invd);
            }
        }
        __syncthreads();   // shared reused by next segment
        pos = segEnd;
    }
}

// ---------------- launch ----------------
extern "C" void kernel_launch(void* const* d_in, const int* in_sizes, int n_in,
                              void* d_out, int out_size) {
    const float* coords = (const float*)d_in[0];
    const float* shape  = (const float*)d_in[1];
    const float* color  = (const float*)d_in[2];
    const float* alpha  = (const float*)d_in[3];
    float* out = (float*)d_out;

    k0_zero<<<(NCELLS + 255) / 256, 256>>>();
    k1_warp_bin<<<N_POINTS / NTHREADS, NTHREADS>>>(coords, out);
    k2_scan_const<<<1, 512>>>(shape, color, alpha);
    k3_scatter<<<N_POINTS / NTHREADS, NTHREADS>>>(out);
    k4_lists<<<(NCELLS * 32) / NTHREADS, NTHREADS>>>(shape);
    k5_blend<<<NB5, NTHREADS>>>(out);
}